// round 8
// baseline (speedup 1.0000x reference)
#include <cuda_runtime.h>
#include <math.h>

// Problem constants (fixed-shape problem)
#define NN   50000
#define EE   1600000
#define KCH  5
#define H1D  32
#define H2D  16
#define PD   12

// ---------------- scratch (static device globals; no allocation) -------------
__device__ int   g_is64;
__device__ float g_deg[NN];
__device__ int   g_cur[NN];       // counts, then CSR cursors
__device__ int   g_off[NN + 1];   // CSR offsets keyed by col (destination)
__device__ int   g_row[EE];
__device__ int   g_col[EE];
__device__ int   g_src[EE];       // CSR: source row per (dst-sorted) edge
__device__ float g_wn [EE];       // CSR: normalized weight per edge
__device__ float g_T1[NN * 32];
__device__ float g_T2[NN * 32];
__device__ float g_T3[NN * 32];
__device__ float g_T4[NN * 32];
__device__ float g_h1[NN * 32];

// ---------------- dtype detection: int64 vs int32 edge_index ----------------
// If edge_index is int64 (little-endian), every odd int32 word is 0
// (values are in [0, 50000)). If int32, odd words are random node ids;
// P(64 consecutive are all zero) ~ (1/50000)^64 ~ 0.
__global__ void k_detect(const int* __restrict__ ei) {
    int nz = 0;
#pragma unroll
    for (int i = 0; i < 64; ++i) nz |= ei[2 * i + 1];
    g_is64 = (nz == 0) ? 1 : 0;
}

__global__ void k_zero() {
    int i = blockIdx.x * blockDim.x + threadIdx.x;
    if (i < NN) { g_deg[i] = 0.f; g_cur[i] = 0; }
}

// Convert indices to int32, accumulate degree (keyed by row) and
// in-degree counts (keyed by col) for the CSR build.
__global__ void k_conv(const int* __restrict__ ei, const float* __restrict__ w) {
    int e = blockIdx.x * blockDim.x + threadIdx.x;
    if (e >= EE) return;
    int r, c;
    if (g_is64) { r = ei[2 * e]; c = ei[2 * (EE + e)]; }
    else        { r = ei[e];     c = ei[EE + e];       }
    g_row[e] = r; g_col[e] = c;
    atomicAdd(&g_deg[r], w[e]);
    atomicAdd(&g_cur[c], 1);
}

// Single-block exclusive scan of counts -> offsets (+ cursor copy).
__global__ void k_scan() {
    __shared__ int sh[1024];
    const int CH = (NN + 1023) / 1024;   // 49
    int t = threadIdx.x;
    int b = t * CH;
    int eend = b + CH; if (eend > NN) eend = NN;
    int s = 0;
    for (int i = b; i < eend; ++i) s += g_cur[i];
    sh[t] = s;
    __syncthreads();
    for (int o = 1; o < 1024; o <<= 1) {
        int v = (t >= o) ? sh[t - o] : 0;
        __syncthreads();
        sh[t] += v;
        __syncthreads();
    }
    int run = sh[t] - s;   // exclusive prefix
    for (int i = b; i < eend; ++i) {
        int c = g_cur[i];
        g_off[i] = run;
        g_cur[i] = run;    // cursor for fill
        run += c;
    }
    if (t == 1023) g_off[NN] = run;   // == EE
}

// Fill CSR: wn = -deg[row]^-1/2 * w * deg[col]^-1/2, scatter by col.
__global__ void k_fill(const float* __restrict__ w) {
    int e = blockIdx.x * blockDim.x + threadIdx.x;
    if (e >= EE) return;
    int r = g_row[e], c = g_col[e];
    float dr = g_deg[r], dc = g_deg[c];
    float ir = dr > 0.f ? rsqrtf(dr) : 0.f;
    float ic = dc > 0.f ? rsqrtf(dc) : 0.f;
    float wn = -ir * w[e] * ic;
    int pos = atomicAdd(&g_cur[c], 1);
    g_src[pos] = r;
    g_wn[pos]  = wn;
}

// Pull-mode spmm + Chebyshev combine: Tout = alpha * (L_hat @ Tin) + beta * Tprev.
// Warp per node, lane = feature (32 wide). Zero atomics; gathers are L2-resident.
__global__ void k_spmm32(const float* __restrict__ Tin, const float* __restrict__ Tprev,
                         float* __restrict__ Tout, float alpha, float beta)
{
    int gw = (blockIdx.x * blockDim.x + threadIdx.x) >> 5;
    if (gw >= NN) return;
    int lane = threadIdx.x & 31;
    int s = g_off[gw], e = g_off[gw + 1];
    float acc = 0.f;
    int j = s;
    for (; j + 4 <= e; j += 4) {
        int   s0 = g_src[j + 0], s1 = g_src[j + 1], s2 = g_src[j + 2], s3 = g_src[j + 3];
        float w0 = g_wn[j + 0],  w1 = g_wn[j + 1],  w2 = g_wn[j + 2],  w3 = g_wn[j + 3];
        float v0 = __ldg(Tin + (size_t)s0 * 32 + lane);
        float v1 = __ldg(Tin + (size_t)s1 * 32 + lane);
        float v2 = __ldg(Tin + (size_t)s2 * 32 + lane);
        float v3 = __ldg(Tin + (size_t)s3 * 32 + lane);
        acc = fmaf(w0, v0, acc);
        acc = fmaf(w1, v1, acc);
        acc = fmaf(w2, v2, acc);
        acc = fmaf(w3, v3, acc);
    }
    for (; j < e; ++j)
        acc = fmaf(g_wn[j], __ldg(Tin + (size_t)g_src[j] * 32 + lane), acc);
    float r = alpha * acc;
    if (beta != 0.f) r = fmaf(beta, Tprev[(size_t)gw * 32 + lane], r);
    Tout[(size_t)gw * 32 + lane] = r;
}

__device__ __forceinline__ float gruact(float z, float h) {
    // H = 0 path: relu((1 - sigmoid(z)) * tanh(h))
    float sg = 1.f / (1.f + expf(-z));
    float v = (1.f - sg) * tanhf(h);
    return fmaxf(v, 0.f);
}

// Cell-1 dense combine: h1[n,:] = act( sum_k T_k[n,:] @ Wz_k + bz ,  ... @ Wh_k + bh )
// Warp handles 2 nodes (lane = output feature j), weights staged in smem,
// inputs broadcast via shfl.
__global__ void k_gemm1(const float* __restrict__ T0, const float* __restrict__ Wx1,
                        const float* __restrict__ bx1, const float* __restrict__ bh1)
{
    __shared__ float sWz[KCH * 32 * 32];
    __shared__ float sWh[KCH * 32 * 32];
    __shared__ float sbz[32], sbh[32];
    int tid = threadIdx.x;
    for (int i = tid; i < KCH * 32 * 32; i += 256) {
        sWz[i] = Wx1[i];                      // gate 0 (z)
        sWh[i] = Wx1[2 * KCH * 32 * 32 + i];  // gate 2 (h)
    }
    if (tid < 32) {
        sbz[tid] = bx1[tid]      + bh1[tid];
        sbh[tid] = bx1[64 + tid] + bh1[64 + tid];
    }
    __syncthreads();
    int warp = tid >> 5, lane = tid & 31;
    int pair = blockIdx.x * 8 + warp;
    if (2 * pair >= NN) return;
    int na = 2 * pair, nb = na + 1;

    float az = sbz[lane], ah = sbh[lane];
    float bz = az,        bh_ = ah;
    const float* const Ts[5] = { T0, g_T1, g_T2, g_T3, g_T4 };
#pragma unroll
    for (int k = 0; k < KCH; ++k) {
        float va = Ts[k][(size_t)na * 32 + lane];
        float vb = Ts[k][(size_t)nb * 32 + lane];
        const float* wz = &sWz[k * 1024];
        const float* wh = &sWh[k * 1024];
#pragma unroll
        for (int i = 0; i < 32; ++i) {
            float ta = __shfl_sync(0xffffffffu, va, i);
            float tb = __shfl_sync(0xffffffffu, vb, i);
            float wzi = wz[i * 32 + lane];
            float whi = wh[i * 32 + lane];
            az  = fmaf(ta, wzi, az);  ah  = fmaf(ta, whi, ah);
            bz  = fmaf(tb, wzi, bz);  bh_ = fmaf(tb, whi, bh_);
        }
    }
    g_h1[(size_t)na * 32 + lane] = gruact(az, ah);
    g_h1[(size_t)nb * 32 + lane] = gruact(bz, bh_);
}

// Cell-2 dense combine + output projection, fully fused:
// half-warp per node (jj = lane&15 = output feature), then h2(16) -> out(12) via shfl.
__global__ void k_gemm2(const float* __restrict__ Wx2, const float* __restrict__ bx2,
                        const float* __restrict__ bh2, const float* __restrict__ Wl,
                        const float* __restrict__ bl,  float* __restrict__ out)
{
    __shared__ float sWz[KCH * 32 * 16];
    __shared__ float sWh[KCH * 32 * 16];
    __shared__ float sbz[16], sbh[16], sWl[256], sbl2[12];
    int tid = threadIdx.x;
    for (int i = tid; i < KCH * 32 * 16; i += 256) {
        sWz[i] = Wx2[i];
        sWh[i] = Wx2[2 * KCH * 32 * 16 + i];
    }
    sWl[tid] = (tid < PD * H2D) ? Wl[tid] : 0.f;   // pad rows 12..15 with zeros
    if (tid < 16) {
        sbz[tid] = bx2[tid]      + bh2[tid];
        sbh[tid] = bx2[32 + tid] + bh2[32 + tid];
    }
    if (tid >= 240 && tid < 240 + PD) sbl2[tid - 240] = bl[tid - 240];
    __syncthreads();
    int warp = tid >> 5, lane = tid & 31;
    int pair = blockIdx.x * 8 + warp;
    if (2 * pair >= NN) return;
    int na = 2 * pair, nb = na + 1;
    int sel = lane >> 4, jj = lane & 15;

    float az = sbz[jj], ah = sbh[jj];
    const float* const Ts[5] = { g_h1, g_T1, g_T2, g_T3, g_T4 };
#pragma unroll
    for (int k = 0; k < KCH; ++k) {
        float va = Ts[k][(size_t)na * 32 + lane];
        float vb = Ts[k][(size_t)nb * 32 + lane];
        const float* wz = &sWz[k * 512];
        const float* wh = &sWh[k * 512];
#pragma unroll
        for (int i = 0; i < 32; ++i) {
            float ta = __shfl_sync(0xffffffffu, va, i);
            float tb = __shfl_sync(0xffffffffu, vb, i);
            float t = sel ? tb : ta;
            az = fmaf(t, wz[i * 16 + jj], az);
            ah = fmaf(t, wh[i * 16 + jj], ah);
        }
    }
    float h2 = gruact(az, ah);

    // out[n, p] = sum_j h2[j] * Wl[p, j] + bl[p];  h2 lives in this half-warp's lanes
    float o = 0.f;
#pragma unroll
    for (int j = 0; j < 16; ++j) {
        float hv = __shfl_sync(0xffffffffu, h2, (lane & 16) | j);
        o = fmaf(hv, sWl[jj * 16 + j], o);
    }
    if (jj < PD) {
        int n = sel ? nb : na;
        out[(size_t)n * PD + jj] = o + sbl2[jj];
    }
}

// -------------------------------- launch --------------------------------
extern "C" void kernel_launch(void* const* d_in, const int* in_sizes, int n_in,
                              void* d_out, int out_size)
{
    const float* x   = (const float*)d_in[0];
    const int*   ei  = (const int*)  d_in[1];   // int32 view; dtype auto-detected
    const float* ew  = (const float*)d_in[2];
    const float* Wx1 = (const float*)d_in[3];
    const float* bx1 = (const float*)d_in[4];
    // d_in[5] = Wh1: dead (H=0)
    const float* bh1 = (const float*)d_in[6];
    const float* Wx2 = (const float*)d_in[7];
    const float* bx2 = (const float*)d_in[8];
    // d_in[9] = Wh2: dead (H=0)
    const float* bh2 = (const float*)d_in[10];
    const float* Wl  = (const float*)d_in[11];
    const float* bl  = (const float*)d_in[12];
    float* out = (float*)d_out;

    float *T1p, *T2p, *T3p, *T4p, *h1p;
    cudaGetSymbolAddress((void**)&T1p, g_T1);
    cudaGetSymbolAddress((void**)&T2p, g_T2);
    cudaGetSymbolAddress((void**)&T3p, g_T3);
    cudaGetSymbolAddress((void**)&T4p, g_T4);
    cudaGetSymbolAddress((void**)&h1p, g_h1);

    const int EB = (EE + 255) / 256;
    const int SB = (NN * 32 + 255) / 256;  // warp-per-node spmm
    const int GB = (NN / 2 + 7) / 8;       // 2 nodes/warp, 8 warps/block

    // CSR build (per replay; ~25us)
    k_detect<<<1, 1>>>(ei);
    k_zero<<<(NN + 255) / 256, 256>>>();
    k_conv<<<EB, 256>>>(ei, ew);
    k_scan<<<1, 1024>>>();
    k_fill<<<EB, 256>>>(ew);

    // Cell 1: Chebyshev T1..T4 on x, then fused gate GEMM + activation -> h1
    k_spmm32<<<SB, 256>>>(x,   x,   T1p, 1.f,  0.f);
    k_spmm32<<<SB, 256>>>(T1p, x,   T2p, 2.f, -1.f);
    k_spmm32<<<SB, 256>>>(T2p, T1p, T3p, 2.f, -1.f);
    k_spmm32<<<SB, 256>>>(T3p, T2p, T4p, 2.f, -1.f);
    k_gemm1<<<GB, 256>>>(x, Wx1, bx1, bh1);

    // Cell 2: Chebyshev T1..T4 on h1, fused gate GEMM + activation + output proj
    k_spmm32<<<SB, 256>>>(h1p, h1p, T1p, 1.f,  0.f);
    k_spmm32<<<SB, 256>>>(T1p, h1p, T2p, 2.f, -1.f);
    k_spmm32<<<SB, 256>>>(T2p, T1p, T3p, 2.f, -1.f);
    k_spmm32<<<SB, 256>>>(T3p, T2p, T4p, 2.f, -1.f);
    k_gemm2<<<GB, 256>>>(Wx2, bx2, bh2, Wl, bl, out);
}

// round 9
// speedup vs baseline: 1.1742x; 1.1742x over previous
#include <cuda_runtime.h>

// Problem constants (fixed-shape problem)
#define NN   50000
#define EE   1600000
#define KCH  5
#define H1D  32
#define H2D  16
#define PD   12
#define NB   49   // ceil(NN/1024)

// ---------------- scratch (static device globals; no allocation) -------------
__device__ int   g_is64;
__device__ float g_deg[NN];
__device__ float g_dis[NN];       // deg^-1/2
__device__ int   g_cnt[NN];       // in-degree counts (keyed by col)
__device__ int   g_cur[NN];       // CSR fill cursors
__device__ int   g_off[NN + 1];   // CSR offsets keyed by col (destination)
__device__ int   g_bsum[NB];      // per-block count sums for the scan
__device__ int2  g_edge[EE];      // CSR: {src row, float bits of wn} per edge
__device__ float g_T1[NN * 32];
__device__ float g_T2[NN * 32];
__device__ float g_T3[NN * 32];
__device__ float g_T4[NN * 32];
__device__ float g_h1[NN * 32];

// ---------------- packed f32x2 FMA (Blackwell FFMA2) ----------------
__device__ __forceinline__ float2 ffma2(float s, float2 b, float2 c) {
    unsigned lo, hi;
    unsigned su = __float_as_uint(s);
    unsigned bx = __float_as_uint(b.x), by = __float_as_uint(b.y);
    unsigned cx = __float_as_uint(c.x), cy = __float_as_uint(c.y);
    asm("{\n\t"
        ".reg .b64 A,B,C,D;\n\t"
        "mov.b64 A, {%2,%2};\n\t"
        "mov.b64 B, {%3,%4};\n\t"
        "mov.b64 C, {%5,%6};\n\t"
        "fma.rn.f32x2 D, A, B, C;\n\t"
        "mov.b64 {%0,%1}, D;\n\t"
        "}"
        : "=r"(lo), "=r"(hi)
        : "r"(su), "r"(bx), "r"(by), "r"(cx), "r"(cy));
    return make_float2(__uint_as_float(lo), __uint_as_float(hi));
}

// ---------------- init: zero accumulators + dtype detection ----------------
// If edge_index is int64 (little-endian), every odd int32 word is 0 (ids < 50000).
__global__ void k_init(const int* __restrict__ ei) {
    int i = blockIdx.x * blockDim.x + threadIdx.x;
    if (i < NN) { g_deg[i] = 0.f; g_cnt[i] = 0; }
    if (i == 0) g_off[NN] = EE;
    if (blockIdx.x == 0 && threadIdx.x < 32) {
        int nz = ei[2 * threadIdx.x + 1] | ei[2 * (threadIdx.x + 32) + 1];
        unsigned m = __ballot_sync(0xffffffffu, nz != 0);
        if (threadIdx.x == 0) g_is64 = (m == 0) ? 1 : 0;
    }
}

// Degree (keyed by row) and in-degree counts (keyed by col).
__global__ void k_conv(const int* __restrict__ ei, const float* __restrict__ w) {
    int e = blockIdx.x * blockDim.x + threadIdx.x;
    if (e >= EE) return;
    int r, c;
    if (g_is64) { r = ei[2 * e]; c = ei[2 * (EE + e)]; }
    else        { r = ei[e];     c = ei[EE + e];       }
    atomicAdd(&g_deg[r], w[e]);
    atomicAdd(&g_cnt[c], 1);
}

// Scan stage A: per-block count sums (49 blocks x 1024), plus dis = deg^-1/2.
__global__ void k_scanA() {
    __shared__ int sw[32];
    int t = threadIdx.x, lane = t & 31, wid = t >> 5;
    int idx = blockIdx.x * 1024 + t;
    int cnt = (idx < NN) ? g_cnt[idx] : 0;
    if (idx < NN) {
        float d = g_deg[idx];
        g_dis[idx] = d > 0.f ? rsqrtf(d) : 0.f;
    }
    int v = cnt;
#pragma unroll
    for (int o = 16; o; o >>= 1) v += __shfl_down_sync(0xffffffffu, v, o);
    if (lane == 0) sw[wid] = v;
    __syncthreads();
    if (wid == 0) {
        int x = sw[lane];
#pragma unroll
        for (int o = 16; o; o >>= 1) x += __shfl_down_sync(0xffffffffu, x, o);
        if (lane == 0) g_bsum[blockIdx.x] = x;
    }
}

// Scan stage C: block-local exclusive scan + base from preceding block sums.
__global__ void k_scanC() {
    __shared__ int s_ws[32];
    __shared__ int s_base;
    int b = blockIdx.x, t = threadIdx.x, lane = t & 31, wid = t >> 5;
    if (wid == 0) {
        int v = 0;
        if (lane < b)      v  = g_bsum[lane];
        if (lane + 32 < b) v += g_bsum[lane + 32];
#pragma unroll
        for (int o = 16; o; o >>= 1) v += __shfl_down_sync(0xffffffffu, v, o);
        if (lane == 0) s_base = v;
    }
    int idx = b * 1024 + t;
    int cnt = (idx < NN) ? g_cnt[idx] : 0;
    int v = cnt;
#pragma unroll
    for (int o = 1; o < 32; o <<= 1) {
        int u = __shfl_up_sync(0xffffffffu, v, o);
        if (lane >= o) v += u;
    }
    if (lane == 31) s_ws[wid] = v;
    __syncthreads();
    if (wid == 0) {
        int w = s_ws[lane];
#pragma unroll
        for (int o = 1; o < 32; o <<= 1) {
            int u = __shfl_up_sync(0xffffffffu, w, o);
            if (lane >= o) w += u;
        }
        s_ws[lane] = w;
    }
    __syncthreads();
    int excl = v - cnt + (wid ? s_ws[wid - 1] : 0) + s_base;
    if (idx < NN) { g_off[idx] = excl; g_cur[idx] = excl; }
}

// Fill CSR: wn = -dis[row] * w * dis[col], scatter by col (interleaved {src, wn}).
__global__ void k_fill(const int* __restrict__ ei, const float* __restrict__ w) {
    int e = blockIdx.x * blockDim.x + threadIdx.x;
    if (e >= EE) return;
    int r, c;
    if (g_is64) { r = ei[2 * e]; c = ei[2 * (EE + e)]; }
    else        { r = ei[e];     c = ei[EE + e];       }
    float wn = -g_dis[r] * w[e] * g_dis[c];
    int pos = atomicAdd(&g_cur[c], 1);
    g_edge[pos] = make_int2(r, __float_as_int(wn));
}

// Pull-mode spmm + Chebyshev combine: Tout = alpha * (L_hat @ Tin) + beta * Tprev.
// Warp per node, lane = feature. Zero atomics; gathers are exactly one 128B line/edge.
__global__ void k_spmm32(const float* __restrict__ Tin, const float* __restrict__ Tprev,
                         float* __restrict__ Tout, float alpha, float beta)
{
    int gw = (blockIdx.x * blockDim.x + threadIdx.x) >> 5;
    if (gw >= NN) return;
    int lane = threadIdx.x & 31;
    int s = g_off[gw], e = g_off[gw + 1];
    float acc = 0.f;
    int j = s;
    for (; j + 4 <= e; j += 4) {
        int2 e0 = g_edge[j + 0], e1 = g_edge[j + 1];
        int2 e2 = g_edge[j + 2], e3 = g_edge[j + 3];
        float v0 = __ldg(Tin + (size_t)e0.x * 32 + lane);
        float v1 = __ldg(Tin + (size_t)e1.x * 32 + lane);
        float v2 = __ldg(Tin + (size_t)e2.x * 32 + lane);
        float v3 = __ldg(Tin + (size_t)e3.x * 32 + lane);
        acc = fmaf(__int_as_float(e0.y), v0, acc);
        acc = fmaf(__int_as_float(e1.y), v1, acc);
        acc = fmaf(__int_as_float(e2.y), v2, acc);
        acc = fmaf(__int_as_float(e3.y), v3, acc);
    }
    for (; j < e; ++j) {
        int2 ed = g_edge[j];
        acc = fmaf(__int_as_float(ed.y), __ldg(Tin + (size_t)ed.x * 32 + lane), acc);
    }
    float r = alpha * acc;
    if (beta != 0.f) r = fmaf(beta, Tprev[(size_t)gw * 32 + lane], r);
    Tout[(size_t)gw * 32 + lane] = r;
}

// H = 0 GRU path: relu((1 - sigmoid(z)) * tanh(h)), MUFU-based fast math (~1e-6 rel)
__device__ __forceinline__ float gruact(float z, float h) {
    float sg = __fdividef(1.f, 1.f + __expf(-z));            // sigmoid
    float th = 1.f - __fdividef(2.f, __expf(2.f * h) + 1.f); // tanh; inf-safe
    float v = (1.f - sg) * th;
    return fmaxf(v, 0.f);
}

// Cell-1 dense combine. Warp handles 2 nodes (lane = output feature),
// {wz,wh} interleaved in smem (one LDS.64 / step), packed FFMA2 accumulators.
__global__ void k_gemm1(const float* __restrict__ T0, const float* __restrict__ Wx1,
                        const float* __restrict__ bx1, const float* __restrict__ bh1)
{
    __shared__ float2 sW[KCH * 32 * 32];    // 40KB: [k][i][lane] -> {wz, wh}
    __shared__ float sbz[32], sbh[32];
    int tid = threadIdx.x;
    for (int i = tid; i < KCH * 32 * 32; i += 256)
        sW[i] = make_float2(Wx1[i], Wx1[2 * KCH * 32 * 32 + i]);  // gates 0 (z), 2 (h)
    if (tid < 32) {
        sbz[tid] = bx1[tid]      + bh1[tid];
        sbh[tid] = bx1[64 + tid] + bh1[64 + tid];
    }
    __syncthreads();
    int warp = tid >> 5, lane = tid & 31;
    int pair = blockIdx.x * 8 + warp;
    if (2 * pair >= NN) return;
    int na = 2 * pair, nb = na + 1;

    float2 accA = make_float2(sbz[lane], sbh[lane]);
    float2 accB = accA;
    const float* const Ts[5] = { T0, g_T1, g_T2, g_T3, g_T4 };
#pragma unroll
    for (int k = 0; k < KCH; ++k) {
        float va = Ts[k][(size_t)na * 32 + lane];
        float vb = Ts[k][(size_t)nb * 32 + lane];
        const float2* w = &sW[k * 1024];
#pragma unroll
        for (int i = 0; i < 32; ++i) {
            float ta = __shfl_sync(0xffffffffu, va, i);
            float tb = __shfl_sync(0xffffffffu, vb, i);
            float2 wi = w[i * 32 + lane];
            accA = ffma2(ta, wi, accA);
            accB = ffma2(tb, wi, accB);
        }
    }
    g_h1[(size_t)na * 32 + lane] = gruact(accA.x, accA.y);
    g_h1[(size_t)nb * 32 + lane] = gruact(accB.x, accB.y);
}

// Cell-2 dense combine + output projection, fully fused.
// Half-warp per node (jj = lane&15 = output feature), then h2(16)->out(12) via shfl.
__global__ void k_gemm2(const float* __restrict__ Wx2, const float* __restrict__ bx2,
                        const float* __restrict__ bh2, const float* __restrict__ Wl,
                        const float* __restrict__ bl,  float* __restrict__ out)
{
    __shared__ float2 sW[KCH * 32 * 16];    // 10KB: [k][i][jj] -> {wz, wh}
    __shared__ float sbz[16], sbh[16], sWl[256], sbl2[12];
    int tid = threadIdx.x;
    for (int i = tid; i < KCH * 32 * 16; i += 256)
        sW[i] = make_float2(Wx2[i], Wx2[2 * KCH * 32 * 16 + i]);
    sWl[tid] = (tid < PD * H2D) ? Wl[tid] : 0.f;   // pad rows 12..15 with zeros
    if (tid < 16) {
        sbz[tid] = bx2[tid]      + bh2[tid];
        sbh[tid] = bx2[32 + tid] + bh2[32 + tid];
    }
    if (tid >= 240 && tid < 240 + PD) sbl2[tid - 240] = bl[tid - 240];
    __syncthreads();
    int warp = tid >> 5, lane = tid & 31;
    int pair = blockIdx.x * 8 + warp;
    if (2 * pair >= NN) return;
    int na = 2 * pair, nb = na + 1;
    int sel = lane >> 4, jj = lane & 15;

    float2 acc = make_float2(sbz[jj], sbh[jj]);
    const float* const Ts[5] = { g_h1, g_T1, g_T2, g_T3, g_T4 };
#pragma unroll
    for (int k = 0; k < KCH; ++k) {
        float va = Ts[k][(size_t)na * 32 + lane];
        float vb = Ts[k][(size_t)nb * 32 + lane];
        const float2* w = &sW[k * 512];
#pragma unroll
        for (int i = 0; i < 32; ++i) {
            float ta = __shfl_sync(0xffffffffu, va, i);
            float tb = __shfl_sync(0xffffffffu, vb, i);
            float t = sel ? tb : ta;
            acc = ffma2(t, w[i * 16 + jj], acc);
        }
    }
    float h2 = gruact(acc.x, acc.y);

    // out[n, p] = sum_j h2[j] * Wl[p, j] + bl[p]; h2 lives in this half-warp's lanes
    float o = 0.f;
#pragma unroll
    for (int j = 0; j < 16; ++j) {
        float hv = __shfl_sync(0xffffffffu, h2, (lane & 16) | j);
        o = fmaf(hv, sWl[jj * 16 + j], o);
    }
    if (jj < PD) {
        int n = sel ? nb : na;
        out[(size_t)n * PD + jj] = o + sbl2[jj];
    }
}

// -------------------------------- launch --------------------------------
extern "C" void kernel_launch(void* const* d_in, const int* in_sizes, int n_in,
                              void* d_out, int out_size)
{
    const float* x   = (const float*)d_in[0];
    const int*   ei  = (const int*)  d_in[1];   // int32 view; dtype auto-detected
    const float* ew  = (const float*)d_in[2];
    const float* Wx1 = (const float*)d_in[3];
    const float* bx1 = (const float*)d_in[4];
    // d_in[5] = Wh1: dead (H=0)
    const float* bh1 = (const float*)d_in[6];
    const float* Wx2 = (const float*)d_in[7];
    const float* bx2 = (const float*)d_in[8];
    // d_in[9] = Wh2: dead (H=0)
    const float* bh2 = (const float*)d_in[10];
    const float* Wl  = (const float*)d_in[11];
    const float* bl  = (const float*)d_in[12];
    float* out = (float*)d_out;

    float *T1p, *T2p, *T3p, *T4p, *h1p;
    cudaGetSymbolAddress((void**)&T1p, g_T1);
    cudaGetSymbolAddress((void**)&T2p, g_T2);
    cudaGetSymbolAddress((void**)&T3p, g_T3);
    cudaGetSymbolAddress((void**)&T4p, g_T4);
    cudaGetSymbolAddress((void**)&h1p, g_h1);

    const int EB = (EE + 255) / 256;
    const int SB = (NN * 32 + 255) / 256;  // warp-per-node spmm
    const int GB = (NN / 2 + 7) / 8;       // 2 nodes/warp, 8 warps/block

    // CSR build
    k_init<<<(NN + 255) / 256, 256>>>(ei);
    k_conv<<<EB, 256>>>(ei, ew);
    k_scanA<<<NB, 1024>>>();
    k_scanC<<<NB, 1024>>>();
    k_fill<<<EB, 256>>>(ei, ew);

    // Cell 1: Chebyshev T1..T4 on x, then fused gate GEMM + activation -> h1
    k_spmm32<<<SB, 256>>>(x,   x,   T1p, 1.f,  0.f);
    k_spmm32<<<SB, 256>>>(T1p, x,   T2p, 2.f, -1.f);
    k_spmm32<<<SB, 256>>>(T2p, T1p, T3p, 2.f, -1.f);
    k_spmm32<<<SB, 256>>>(T3p, T2p, T4p, 2.f, -1.f);
    k_gemm1<<<GB, 256>>>(x, Wx1, bx1, bh1);

    // Cell 2: Chebyshev T1..T4 on h1, fused gate GEMM + activation + output proj
    k_spmm32<<<SB, 256>>>(h1p, h1p, T1p, 1.f,  0.f);
    k_spmm32<<<SB, 256>>>(T1p, h1p, T2p, 2.f, -1.f);
    k_spmm32<<<SB, 256>>>(T2p, T1p, T3p, 2.f, -1.f);
    k_spmm32<<<SB, 256>>>(T3p, T2p, T4p, 2.f, -1.f);
    k_gemm2<<<GB, 256>>>(Wx2, bx2, bh2, Wl, bl, out);
}

// round 10
// speedup vs baseline: 1.4125x; 1.2029x over previous
#include <cuda_runtime.h>
#include <cuda_fp16.h>

// Problem constants (fixed-shape problem)
#define NN   50000
#define EE   1600000
#define KCH  5
#define H1D  32
#define H2D  16
#define PD   12
#define NB   49   // ceil(NN/1024)

// ---------------- scratch (static device globals; no allocation) -------------
__device__ int     g_is64;
__device__ float   g_deg[NN];
__device__ float   g_dis[NN];       // deg^-1/2
__device__ int     g_cnt[NN];       // in-degree counts (keyed by col)
__device__ int     g_cur[NN];       // CSR fill cursors
__device__ int     g_off[NN + 1];   // CSR offsets keyed by col (destination)
__device__ int     g_bsum[NB];      // per-block count sums for the scan
__device__ int2    g_edge[EE];      // CSR: {src row, float bits of wn} per edge
// fp16 node-feature buffers: one row = 32 halves = 16 half2 = 64B
__device__ __half2 g_Xh [NN * 16];  // x converted to fp16
__device__ __half2 g_T1h[NN * 16];
__device__ __half2 g_T2h[NN * 16];
__device__ __half2 g_T3h[NN * 16];
__device__ __half2 g_T4h[NN * 16];
__device__ __half2 g_h1h[NN * 16];

// ---------------- packed f32x2 FMA (Blackwell FFMA2) ----------------
__device__ __forceinline__ float2 ffma2(float s, float2 b, float2 c) {
    unsigned lo, hi;
    unsigned su = __float_as_uint(s);
    unsigned bx = __float_as_uint(b.x), by = __float_as_uint(b.y);
    unsigned cx = __float_as_uint(c.x), cy = __float_as_uint(c.y);
    asm("{\n\t"
        ".reg .b64 A,B,C,D;\n\t"
        "mov.b64 A, {%2,%2};\n\t"
        "mov.b64 B, {%3,%4};\n\t"
        "mov.b64 C, {%5,%6};\n\t"
        "fma.rn.f32x2 D, A, B, C;\n\t"
        "mov.b64 {%0,%1}, D;\n\t"
        "}"
        : "=r"(lo), "=r"(hi)
        : "r"(su), "r"(bx), "r"(by), "r"(cx), "r"(cy));
    return make_float2(__uint_as_float(lo), __uint_as_float(hi));
}

// ---------------- init: zero accumulators + x->fp16 + dtype detection -------
// If edge_index is int64 (little-endian), every odd int32 word is 0 (ids < 50000).
__global__ void k_init(const int* __restrict__ ei, const float* __restrict__ x) {
    int i = blockIdx.x * blockDim.x + threadIdx.x;
    if (i < NN * 16) {
        float2 v = ((const float2*)x)[i];
        g_Xh[i] = __floats2half2_rn(v.x, v.y);
    }
    if (i < NN) { g_deg[i] = 0.f; g_cnt[i] = 0; }
    if (i == 0) g_off[NN] = EE;
    if (blockIdx.x == 0 && threadIdx.x < 32) {
        int nz = ei[2 * threadIdx.x + 1] | ei[2 * (threadIdx.x + 32) + 1];
        unsigned m = __ballot_sync(0xffffffffu, nz != 0);
        if (threadIdx.x == 0) g_is64 = (m == 0) ? 1 : 0;
    }
}

// Degree (keyed by row) and in-degree counts (keyed by col).
__global__ void k_conv(const int* __restrict__ ei, const float* __restrict__ w) {
    int e = blockIdx.x * blockDim.x + threadIdx.x;
    if (e >= EE) return;
    int r, c;
    if (g_is64) { r = ei[2 * e]; c = ei[2 * (EE + e)]; }
    else        { r = ei[e];     c = ei[EE + e];       }
    atomicAdd(&g_deg[r], w[e]);
    atomicAdd(&g_cnt[c], 1);
}

// Scan stage A: per-block count sums (49 blocks x 1024), plus dis = deg^-1/2.
__global__ void k_scanA() {
    __shared__ int sw[32];
    int t = threadIdx.x, lane = t & 31, wid = t >> 5;
    int idx = blockIdx.x * 1024 + t;
    int cnt = (idx < NN) ? g_cnt[idx] : 0;
    if (idx < NN) {
        float d = g_deg[idx];
        g_dis[idx] = d > 0.f ? rsqrtf(d) : 0.f;
    }
    int v = cnt;
#pragma unroll
    for (int o = 16; o; o >>= 1) v += __shfl_down_sync(0xffffffffu, v, o);
    if (lane == 0) sw[wid] = v;
    __syncthreads();
    if (wid == 0) {
        int x = sw[lane];
#pragma unroll
        for (int o = 16; o; o >>= 1) x += __shfl_down_sync(0xffffffffu, x, o);
        if (lane == 0) g_bsum[blockIdx.x] = x;
    }
}

// Scan stage C: block-local exclusive scan + base from preceding block sums.
__global__ void k_scanC() {
    __shared__ int s_ws[32];
    __shared__ int s_base;
    int b = blockIdx.x, t = threadIdx.x, lane = t & 31, wid = t >> 5;
    if (wid == 0) {
        int v = 0;
        if (lane < b)      v  = g_bsum[lane];
        if (lane + 32 < b) v += g_bsum[lane + 32];
#pragma unroll
        for (int o = 16; o; o >>= 1) v += __shfl_down_sync(0xffffffffu, v, o);
        if (lane == 0) s_base = v;
    }
    int idx = b * 1024 + t;
    int cnt = (idx < NN) ? g_cnt[idx] : 0;
    int v = cnt;
#pragma unroll
    for (int o = 1; o < 32; o <<= 1) {
        int u = __shfl_up_sync(0xffffffffu, v, o);
        if (lane >= o) v += u;
    }
    if (lane == 31) s_ws[wid] = v;
    __syncthreads();
    if (wid == 0) {
        int w = s_ws[lane];
#pragma unroll
        for (int o = 1; o < 32; o <<= 1) {
            int u = __shfl_up_sync(0xffffffffu, w, o);
            if (lane >= o) w += u;
        }
        s_ws[lane] = w;
    }
    __syncthreads();
    int excl = v - cnt + (wid ? s_ws[wid - 1] : 0) + s_base;
    if (idx < NN) { g_off[idx] = excl; g_cur[idx] = excl; }
}

// Fill CSR: wn = -dis[row] * w * dis[col], scatter by col (interleaved {src, wn}).
__global__ void k_fill(const int* __restrict__ ei, const float* __restrict__ w) {
    int e = blockIdx.x * blockDim.x + threadIdx.x;
    if (e >= EE) return;
    int r, c;
    if (g_is64) { r = ei[2 * e]; c = ei[2 * (EE + e)]; }
    else        { r = ei[e];     c = ei[EE + e];       }
    float wn = -g_dis[r] * w[e] * g_dis[c];
    int pos = atomicAdd(&g_cur[c], 1);
    g_edge[pos] = make_int2(r, __float_as_int(wn));
}

// Pull-mode fp16 spmm + Chebyshev combine: Tout = alpha*(L_hat @ Tin) + beta*Tprev.
// Warp per node; node row = 32 halves = 16 half2 -> HALF-warp covers a row, so
// the two half-warps process two DIFFERENT edges per LDG instruction.
// Accumulation in fp32; shfl-xor(16) combines the two halves' partial sums.
__global__ void k_spmm16(const __half2* __restrict__ Tin, const __half2* __restrict__ Tprev,
                         __half2* __restrict__ Tout, float alpha, float beta)
{
    int gw = (blockIdx.x * blockDim.x + threadIdx.x) >> 5;
    if (gw >= NN) return;
    int lane = threadIdx.x & 31;
    int h = lane >> 4, l = lane & 15;
    int s = g_off[gw], e = g_off[gw + 1];
    float accx = 0.f, accy = 0.f;
    int j = s;
    for (; j + 4 <= e; j += 4) {
        int2 ea = __ldg(&g_edge[j + h]);        // halves take edges j / j+1
        int2 eb = __ldg(&g_edge[j + 2 + h]);    // and j+2 / j+3
        float2 va = __half22float2(__ldg(&Tin[(size_t)ea.x * 16 + l]));
        float2 vb = __half22float2(__ldg(&Tin[(size_t)eb.x * 16 + l]));
        float wa = __int_as_float(ea.y), wb = __int_as_float(eb.y);
        accx = fmaf(wa, va.x, accx); accy = fmaf(wa, va.y, accy);
        accx = fmaf(wb, vb.x, accx); accy = fmaf(wb, vb.y, accy);
    }
    if (j + 2 <= e) {
        int2 ea = __ldg(&g_edge[j + h]);
        float2 va = __half22float2(__ldg(&Tin[(size_t)ea.x * 16 + l]));
        float wa = __int_as_float(ea.y);
        accx = fmaf(wa, va.x, accx); accy = fmaf(wa, va.y, accy);
        j += 2;
    }
    if (j < e && h == 0) {                      // odd tail: half 0 only
        int2 ea = __ldg(&g_edge[j]);
        float2 va = __half22float2(__ldg(&Tin[(size_t)ea.x * 16 + l]));
        float wa = __int_as_float(ea.y);
        accx = fmaf(wa, va.x, accx); accy = fmaf(wa, va.y, accy);
    }
    accx += __shfl_xor_sync(0xffffffffu, accx, 16);
    accy += __shfl_xor_sync(0xffffffffu, accy, 16);
    if (h == 0) {
        float rx = alpha * accx, ry = alpha * accy;
        if (beta != 0.f) {
            float2 tp = __half22float2(Tprev[(size_t)gw * 16 + l]);
            rx = fmaf(beta, tp.x, rx);
            ry = fmaf(beta, tp.y, ry);
        }
        Tout[(size_t)gw * 16 + l] = __floats2half2_rn(rx, ry);
    }
}

// H = 0 GRU path: relu((1 - sigmoid(z)) * tanh(h)), MUFU-based fast math
__device__ __forceinline__ float gruact(float z, float h) {
    float sg = __fdividef(1.f, 1.f + __expf(-z));            // sigmoid
    float th = 1.f - __fdividef(2.f, __expf(2.f * h) + 1.f); // tanh; inf-safe
    float v = (1.f - sg) * th;
    return fmaxf(v, 0.f);
}

// Cell-1 dense combine. Warp handles 2 nodes (lane = output feature),
// {wz,wh} interleaved in smem (one LDS.64 / step), packed FFMA2 accumulators.
// T0 = x read fp32 (exact); T1..T4 read fp16. Result h1 written fp16.
__global__ void k_gemm1(const float* __restrict__ x, const float* __restrict__ Wx1,
                        const float* __restrict__ bx1, const float* __restrict__ bh1)
{
    __shared__ float2 sW[KCH * 32 * 32];    // 40KB: [k][i][lane] -> {wz, wh}
    __shared__ float sbz[32], sbh[32];
    int tid = threadIdx.x;
    for (int i = tid; i < KCH * 32 * 32; i += 256)
        sW[i] = make_float2(Wx1[i], Wx1[2 * KCH * 32 * 32 + i]);  // gates 0 (z), 2 (h)
    if (tid < 32) {
        sbz[tid] = bx1[tid]      + bh1[tid];
        sbh[tid] = bx1[64 + tid] + bh1[64 + tid];
    }
    __syncthreads();
    int warp = tid >> 5, lane = tid & 31;
    int pair = blockIdx.x * 8 + warp;
    if (2 * pair >= NN) return;
    int na = 2 * pair, nb = na + 1;

    float2 accA = make_float2(sbz[lane], sbh[lane]);
    float2 accB = accA;
    const __half* const Ts[4] = { (const __half*)g_T1h, (const __half*)g_T2h,
                                  (const __half*)g_T3h, (const __half*)g_T4h };
#pragma unroll
    for (int k = 0; k < KCH; ++k) {
        float va, vb;
        if (k == 0) {
            va = x[(size_t)na * 32 + lane];
            vb = x[(size_t)nb * 32 + lane];
        } else {
            va = __half2float(Ts[k - 1][(size_t)na * 32 + lane]);
            vb = __half2float(Ts[k - 1][(size_t)nb * 32 + lane]);
        }
        const float2* w = &sW[k * 1024];
#pragma unroll
        for (int i = 0; i < 32; ++i) {
            float ta = __shfl_sync(0xffffffffu, va, i);
            float tb = __shfl_sync(0xffffffffu, vb, i);
            float2 wi = w[i * 32 + lane];
            accA = ffma2(ta, wi, accA);
            accB = ffma2(tb, wi, accB);
        }
    }
    __half* h1 = (__half*)g_h1h;
    h1[(size_t)na * 32 + lane] = __float2half_rn(gruact(accA.x, accA.y));
    h1[(size_t)nb * 32 + lane] = __float2half_rn(gruact(accB.x, accB.y));
}

// Cell-2 dense combine + output projection, fully fused.
// Half-warp per node (jj = lane&15 = output feature), then h2(16)->out(12) via shfl.
__global__ void k_gemm2(const float* __restrict__ Wx2, const float* __restrict__ bx2,
                        const float* __restrict__ bh2, const float* __restrict__ Wl,
                        const float* __restrict__ bl,  float* __restrict__ out)
{
    __shared__ float2 sW[KCH * 32 * 16];    // 10KB: [k][i][jj] -> {wz, wh}
    __shared__ float sbz[16], sbh[16], sWl[256], sbl2[12];
    int tid = threadIdx.x;
    for (int i = tid; i < KCH * 32 * 16; i += 256)
        sW[i] = make_float2(Wx2[i], Wx2[2 * KCH * 32 * 16 + i]);
    sWl[tid] = (tid < PD * H2D) ? Wl[tid] : 0.f;   // pad rows 12..15 with zeros
    if (tid < 16) {
        sbz[tid] = bx2[tid]      + bh2[tid];
        sbh[tid] = bx2[32 + tid] + bh2[32 + tid];
    }
    if (tid >= 240 && tid < 240 + PD) sbl2[tid - 240] = bl[tid - 240];
    __syncthreads();
    int warp = tid >> 5, lane = tid & 31;
    int pair = blockIdx.x * 8 + warp;
    if (2 * pair >= NN) return;
    int na = 2 * pair, nb = na + 1;
    int sel = lane >> 4, jj = lane & 15;

    float2 acc = make_float2(sbz[jj], sbh[jj]);
    const __half* const Ts[5] = { (const __half*)g_h1h, (const __half*)g_T1h,
                                  (const __half*)g_T2h, (const __half*)g_T3h,
                                  (const __half*)g_T4h };
#pragma unroll
    for (int k = 0; k < KCH; ++k) {
        float va = __half2float(Ts[k][(size_t)na * 32 + lane]);
        float vb = __half2float(Ts[k][(size_t)nb * 32 + lane]);
        const float2* w = &sW[k * 512];
#pragma unroll
        for (int i = 0; i < 32; ++i) {
            float ta = __shfl_sync(0xffffffffu, va, i);
            float tb = __shfl_sync(0xffffffffu, vb, i);
            float t = sel ? tb : ta;
            acc = ffma2(t, w[i * 16 + jj], acc);
        }
    }
    float h2 = gruact(acc.x, acc.y);

    // out[n, p] = sum_j h2[j] * Wl[p, j] + bl[p]; h2 lives in this half-warp's lanes
    float o = 0.f;
#pragma unroll
    for (int j = 0; j < 16; ++j) {
        float hv = __shfl_sync(0xffffffffu, h2, (lane & 16) | j);
        o = fmaf(hv, sWl[jj * 16 + j], o);
    }
    if (jj < PD) {
        int n = sel ? nb : na;
        out[(size_t)n * PD + jj] = o + sbl2[jj];
    }
}

// -------------------------------- launch --------------------------------
extern "C" void kernel_launch(void* const* d_in, const int* in_sizes, int n_in,
                              void* d_out, int out_size)
{
    const float* x   = (const float*)d_in[0];
    const int*   ei  = (const int*)  d_in[1];   // int32 view; dtype auto-detected
    const float* ew  = (const float*)d_in[2];
    const float* Wx1 = (const float*)d_in[3];
    const float* bx1 = (const float*)d_in[4];
    // d_in[5] = Wh1: dead (H=0)
    const float* bh1 = (const float*)d_in[6];
    const float* Wx2 = (const float*)d_in[7];
    const float* bx2 = (const float*)d_in[8];
    // d_in[9] = Wh2: dead (H=0)
    const float* bh2 = (const float*)d_in[10];
    const float* Wl  = (const float*)d_in[11];
    const float* bl  = (const float*)d_in[12];
    float* out = (float*)d_out;

    __half2 *Xh, *T1p, *T2p, *T3p, *T4p, *h1p;
    cudaGetSymbolAddress((void**)&Xh,  g_Xh);
    cudaGetSymbolAddress((void**)&T1p, g_T1h);
    cudaGetSymbolAddress((void**)&T2p, g_T2h);
    cudaGetSymbolAddress((void**)&T3p, g_T3h);
    cudaGetSymbolAddress((void**)&T4p, g_T4h);
    cudaGetSymbolAddress((void**)&h1p, g_h1h);

    const int EB = (EE + 255) / 256;
    const int SB = (NN * 32 + 255) / 256;  // warp-per-node spmm
    const int GB = (NN / 2 + 7) / 8;       // 2 nodes/warp, 8 warps/block

    // CSR build (+ x -> fp16 conversion inside k_init)
    k_init<<<(NN * 16 + 255) / 256, 256>>>(ei, x);
    k_conv<<<EB, 256>>>(ei, ew);
    k_scanA<<<NB, 1024>>>();
    k_scanC<<<NB, 1024>>>();
    k_fill<<<EB, 256>>>(ei, ew);

    // Cell 1: Chebyshev T1..T4 on x (fp16), then fused gate GEMM + act -> h1
    k_spmm16<<<SB, 256>>>(Xh,  Xh,  T1p, 1.f,  0.f);
    k_spmm16<<<SB, 256>>>(T1p, Xh,  T2p, 2.f, -1.f);
    k_spmm16<<<SB, 256>>>(T2p, T1p, T3p, 2.f, -1.f);
    k_spmm16<<<SB, 256>>>(T3p, T2p, T4p, 2.f, -1.f);
    k_gemm1<<<GB, 256>>>(x, Wx1, bx1, bh1);

    // Cell 2: Chebyshev T1..T4 on h1, fused gate GEMM + activation + output proj
    k_spmm16<<<SB, 256>>>(h1p, h1p, T1p, 1.f,  0.f);
    k_spmm16<<<SB, 256>>>(T1p, h1p, T2p, 2.f, -1.f);
    k_spmm16<<<SB, 256>>>(T2p, T1p, T3p, 2.f, -1.f);
    k_spmm16<<<SB, 256>>>(T3p, T2p, T4p, 2.f, -1.f);
    k_gemm2<<<GB, 256>>>(Wx2, bx2, bh2, Wl, bl, out);
}